// round 9
// baseline (speedup 1.0000x reference)
#include <cuda_runtime.h>
#include <math.h>

#define Bc 4
#define Nc 100000
#define Kc 128
#define Q_MIN 0.5f
#define HUBER_D 2.0f
#define EPS_CLIP 1e-4f

// ---------------- device scratch (no allocations allowed) ----------------
__device__ unsigned long long g_cand[Bc * Kc];   // packed (beta_bits<<32)|(~n)
__device__ float4             g_obj[Bc * Kc];    // x0, x1, q_alpha*exf, unused
__device__ double             g_acc[10];
// acc: 0=att 1=rep 2=noise_beta 3=noise_cnt 4=p_sum 5=pE 6=pPos 7=pT 8=n_obj 9=beta_obj

__device__ __forceinline__ float clipb(float b) {
    return fminf(fmaxf(b, EPS_CLIP), 1.0f - EPS_CLIP);
}

// ---------------- kernel A: reset scratch ----------------
__global__ void k_init() {
    int t = threadIdx.x;
    if (t < Bc * Kc) g_cand[t] = 0ULL;
    if (t < 10) g_acc[t] = 0.0;
}

// ---------------- kernel B: per-object argmax (on clipped beta) ----------------
__global__ void k_argmax(const float* __restrict__ beta,
                         const int* __restrict__ t_idx) {
    int i = blockIdx.x * blockDim.x + threadIdx.x;
    if (i >= Bc * Nc) return;
    int obj = t_idx[i] - 1;
    if (obj < 0 || obj >= Kc) return;
    float b = clipb(beta[i]);
    unsigned int fb = __float_as_uint(b);           // b > 0 -> order-preserving
    unsigned int n  = (unsigned int)(i % Nc);
    unsigned long long key =
        ((unsigned long long)fb << 32) | (unsigned long long)(0xFFFFFFFFu - n);
    atomicMax(&g_cand[(i / Nc) * Kc + obj], key);
}

// ---------------- kernel C: gather condensation points ----------------
__global__ void k_gather(const float* __restrict__ beta,
                         const float* __restrict__ ccoords) {
    int t = threadIdx.x;            // 0..511 == (b,k)
    int b = t / Kc;
    unsigned long long key = g_cand[t];
    float4 o = make_float4(0.f, 0.f, 0.f, 0.f);
    float exf = 0.f, bobj = 0.f;
    if (key != 0ULL) {
        unsigned int n = 0xFFFFFFFFu - (unsigned int)(key & 0xFFFFFFFFu);
        int i = b * Nc + (int)n;
        float bc = clipb(beta[i]);
        float a  = atanhf(bc);
        o.x = ccoords[2 * i];
        o.y = ccoords[2 * i + 1];
        o.z = a * a + Q_MIN;        // q_alpha (exists==1 baked in; 0 otherwise)
        exf  = 1.f;
        bobj = 1.f - bc;
    }
    g_obj[t] = o;
    atomicAdd(&g_acc[8], (double)exf);
    atomicAdd(&g_acc[9], (double)bobj);
}

// ---------------- kernel D: main pairwise + payload pass ----------------
__global__ void __launch_bounds__(256, 4)
k_main(const float* __restrict__ beta,
       const float* __restrict__ ccoords,
       const float* __restrict__ pred_energy,
       const float* __restrict__ pred_pos,
       const float* __restrict__ pred_time,
       const float* __restrict__ t_energy,
       const float* __restrict__ t_pos,
       const float* __restrict__ t_time,
       const int*   __restrict__ t_idx) {
    __shared__ float4 so[Kc];
    const int b = blockIdx.y;
    const int t = threadIdx.x;
    if (t < Kc) so[t] = g_obj[b * Kc + t];
    __syncthreads();

    float att = 0.f, rep = 0.f, nb = 0.f, nc = 0.f;
    float ps = 0.f, pes = 0.f, pps = 0.f, pts = 0.f;

    int n = blockIdx.x * 256 + t;
    if (n < Nc) {
        int i = b * Nc + n;
        float bc = clipb(beta[i]);
        float a  = atanhf(bc);
        float q  = fmaf(a, a, Q_MIN);
        int   ti = t_idx[i];
        int  obj = ti - 1;
        float2 xc = ((const float2*)ccoords)[i];

        // payload & noise terms
        float noise = (ti == 0) ? 1.0f : 0.0f;
        float p = a * a * (1.0f - noise);
        nc = noise;
        nb = bc * noise;
        float de  = pred_energy[i] - t_energy[i];
        float ade = fabsf(de);
        float hub = (ade <= HUBER_D) ? 0.5f * de * de
                                     : HUBER_D * (ade - 0.5f * HUBER_D);
        float2 pp2 = ((const float2*)pred_pos)[i];
        float2 tp2 = ((const float2*)t_pos)[i];
        float d0 = pp2.x - tp2.x, d1 = pp2.y - tp2.y;
        float dtm = pred_time[i] - t_time[i];
        ps  = p;
        pes = p * hub;
        pps = p * (d0 * d0 + d1 * d1);
        pts = p * dtm * dtm;

        // repulsive sum over ALL objects (member removed afterwards)
        float racc = 0.f;
        #pragma unroll 8
        for (int k = 0; k < Kc; ++k) {
            float4 o = so[k];
            float dx = xc.x - o.x;
            float dy = xc.y - o.y;
            float d2 = fmaf(dx, dx, fmaf(dy, dy, 1e-12f));
            float dist = d2 * rsqrtf(d2);
            racc = fmaf(o.z, fmaxf(1.0f - dist, 0.0f), racc);
        }
        if (obj >= 0) {
            float4 o = so[obj];
            float dx = xc.x - o.x;
            float dy = xc.y - o.y;
            float d2 = fmaf(dx, dx, fmaf(dy, dy, 1e-12f));
            float dist = d2 * rsqrtf(d2);
            racc -= o.z * fmaxf(1.0f - dist, 0.0f);   // exclude member from rep
            att = q * o.z * d2;                        // attractive term
        }
        rep = q * racc;
    }

    // ---- block reduction of 8 scalars ----
    float v[8] = {att, rep, nb, nc, ps, pes, pps, pts};
    #pragma unroll
    for (int off = 16; off > 0; off >>= 1) {
        #pragma unroll
        for (int j = 0; j < 8; ++j)
            v[j] += __shfl_down_sync(0xFFFFFFFFu, v[j], off);
    }
    __shared__ float sred[8][8];
    int wid = t >> 5, lid = t & 31;
    if (lid == 0) {
        #pragma unroll
        for (int j = 0; j < 8; ++j) sred[j][wid] = v[j];
    }
    __syncthreads();
    if (t < 8) {
        float s = 0.f;
        #pragma unroll
        for (int w = 0; w < 8; ++w) s += sred[t][w];
        atomicAdd(&g_acc[t], (double)s);
    }
}

// ---------------- kernel E: finalize scalar ----------------
__global__ void k_final(float* __restrict__ out) {
    double ntot   = (double)(Bc * Nc);
    double L_att  = g_acc[0] / ntot;
    double L_rep  = g_acc[1] / ntot;
    double n_obj  = fmax(g_acc[8], 1.0);
    double L_bobj = g_acc[9] / n_obj;
    double n_noi  = fmax(g_acc[3], 1.0);
    double L_noi  = g_acc[2] / n_noi;
    double psum   = fmax(g_acc[4], 1e-6);
    double L_e    = g_acc[5] / psum;
    double L_p    = g_acc[6] / psum;
    double L_t    = g_acc[7] / psum;
    out[0] = (float)(L_att + L_rep + (L_bobj + L_noi) + L_e + L_p + L_t);
}

// ---------------- launch ----------------
extern "C" void kernel_launch(void* const* d_in, const int* in_sizes, int n_in,
                              void* d_out, int out_size) {
    const float* beta        = (const float*)d_in[0];
    const float* ccoords     = (const float*)d_in[1];
    const float* pred_energy = (const float*)d_in[2];
    const float* pred_pos    = (const float*)d_in[3];
    const float* pred_time   = (const float*)d_in[4];
    const float* t_energy    = (const float*)d_in[5];
    const float* t_pos       = (const float*)d_in[6];
    const float* t_time      = (const float*)d_in[7];
    const int*   t_idx       = (const int*)d_in[8];
    float* out = (float*)d_out;

    k_init<<<1, 512>>>();
    k_argmax<<<(Bc * Nc + 255) / 256, 256>>>(beta, t_idx);
    k_gather<<<1, Bc * Kc>>>(beta, ccoords);
    dim3 grid((Nc + 255) / 256, Bc);
    k_main<<<grid, 256>>>(beta, ccoords, pred_energy, pred_pos, pred_time,
                          t_energy, t_pos, t_time, t_idx);
    k_final<<<1, 1>>>(out);
}

// round 10
// speedup vs baseline: 1.0568x; 1.0568x over previous
#include <cuda_runtime.h>
#include <math.h>

#define Bc 4
#define Nc 100000
#define Kc 128
#define Q_MIN 0.5f
#define HUBER_D 2.0f
#define EPS_CLIP 1e-4f

#define GRID_N ((Nc + 255) / 256)           // 391
#define TOTAL_BLOCKS (GRID_N * Bc)          // 1564

typedef unsigned long long ull;

// ---------------- device scratch (zero at load; finalizer re-zeros) ----------
__device__ ull          g_cand[Bc * Kc];    // packed (beta_bits<<32)|(~n)
__device__ double       g_acc[8];           // 0=att 1=rep 2=nb 3=nc 4=ps 5=pE 6=pPos 7=pT
__device__ unsigned int g_done;

// ---------------- packed f32x2 helpers (sm_103a) ------------------------------
#define PACKF(out, lo, hi) \
    asm("mov.b64 %0, {%1, %2};" : "=l"(out) : "r"(__float_as_uint(lo)), "r"(__float_as_uint(hi)))
#define UNPACKF(lo, hi, in) do { unsigned int _a, _b; \
    asm("mov.b64 {%0, %1}, %2;" : "=r"(_a), "=r"(_b) : "l"(in)); \
    (lo) = __uint_as_float(_a); (hi) = __uint_as_float(_b); } while (0)
#define ADD2(out, a, b)    asm("add.rn.f32x2 %0, %1, %2;"     : "=l"(out) : "l"(a), "l"(b))
#define MUL2(out, a, b)    asm("mul.rn.f32x2 %0, %1, %2;"     : "=l"(out) : "l"(a), "l"(b))
#define FMA2(out, a, b, c) asm("fma.rn.f32x2 %0, %1, %2, %3;" : "=l"(out) : "l"(a), "l"(b), "l"(c))

__device__ __forceinline__ float rsq(float x) {
    float r; asm("rsqrt.approx.f32 %0, %1;" : "=f"(r) : "f"(x)); return r;
}
__device__ __forceinline__ float clipb(float b) {
    return fminf(fmaxf(b, EPS_CLIP), 1.0f - EPS_CLIP);
}

// ---------------- kernel 1: argmax + per-hit payload losses ------------------
__global__ void __launch_bounds__(256)
k_pass1(const float* __restrict__ beta,
        const int*   __restrict__ t_idx,
        const float* __restrict__ pred_energy,
        const float* __restrict__ pred_pos,
        const float* __restrict__ pred_time,
        const float* __restrict__ t_energy,
        const float* __restrict__ t_pos,
        const float* __restrict__ t_time) {
    const int b = blockIdx.y;
    const int t = threadIdx.x;
    const int n = blockIdx.x * 256 + t;

    float nb = 0.f, nc = 0.f, ps = 0.f, pes = 0.f, pps = 0.f, pts = 0.f;
    if (n < Nc) {
        int i  = b * Nc + n;
        int ti = t_idx[i];
        float bc = clipb(beta[i]);
        if (ti > 0) {  // member of object ti-1: feed segment-argmax
            unsigned int fb = __float_as_uint(bc);
            ull key = ((ull)fb << 32) | (ull)(0xFFFFFFFFu - (unsigned int)n);
            atomicMax(&g_cand[b * Kc + (ti - 1)], key);
        }
        float a = atanhf(bc);
        float noise = (ti == 0) ? 1.0f : 0.0f;
        float p = a * a * (1.0f - noise);
        nc = noise;
        nb = bc * noise;
        float de  = pred_energy[i] - t_energy[i];
        float ade = fabsf(de);
        float hub = (ade <= HUBER_D) ? 0.5f * de * de
                                     : HUBER_D * (ade - 0.5f * HUBER_D);
        float2 pp2 = ((const float2*)pred_pos)[i];
        float2 tp2 = ((const float2*)t_pos)[i];
        float d0 = pp2.x - tp2.x, d1 = pp2.y - tp2.y;
        float dtm = pred_time[i] - t_time[i];
        ps  = p;
        pes = p * hub;
        pps = p * (d0 * d0 + d1 * d1);
        pts = p * dtm * dtm;
    }

    float v[6] = {nb, nc, ps, pes, pps, pts};
    #pragma unroll
    for (int off = 16; off > 0; off >>= 1)
        #pragma unroll
        for (int j = 0; j < 6; ++j)
            v[j] += __shfl_down_sync(0xFFFFFFFFu, v[j], off);
    __shared__ float sred[6][8];
    int wid = t >> 5, lid = t & 31;
    if (lid == 0)
        #pragma unroll
        for (int j = 0; j < 6; ++j) sred[j][wid] = v[j];
    __syncthreads();
    if (t < 6) {
        float s = 0.f;
        #pragma unroll
        for (int w = 0; w < 8; ++w) s += sred[t][w];
        atomicAdd(&g_acc[2 + t], (double)s);
    }
}

// ---------------- kernel 2: pair loop + fused finalize ------------------------
__global__ void __launch_bounds__(256)
k_pair(const float* __restrict__ beta,
       const float* __restrict__ ccoords,
       const int*   __restrict__ t_idx,
       float*       __restrict__ out) {
    __shared__ ull sxn[Kc / 2], syn[Kc / 2], sqz[Kc / 2];   // negated x, negated y, q_alpha*exf
    __shared__ float sr[2][8];
    __shared__ bool s_last;

    const int b = blockIdx.y;
    const int t = threadIdx.x;

    // per-block gather of condensation points (L2-cached after first block)
    if (t < Kc) {
        ull key = g_cand[b * Kc + t];
        float xn = 0.f, yn = 0.f, qz = 0.f;
        if (key != 0ULL) {
            unsigned int nn = 0xFFFFFFFFu - (unsigned int)key;
            int ii = b * Nc + (int)nn;
            float bc = clipb(beta[ii]);
            float a  = atanhf(bc);
            qz = fmaf(a, a, Q_MIN);
            float2 c = ((const float2*)ccoords)[ii];
            xn = -c.x; yn = -c.y;
        }
        ((float*)sxn)[t] = xn;
        ((float*)syn)[t] = yn;
        ((float*)sqz)[t] = qz;
    }
    __syncthreads();

    float att = 0.f, rep = 0.f;
    const int n = blockIdx.x * 256 + t;
    if (n < Nc) {
        int i = b * Nc + n;
        float bc = clipb(beta[i]);
        float a  = atanhf(bc);
        float q  = fmaf(a, a, Q_MIN);
        float2 xc = ((const float2*)ccoords)[i];

        ull xx, yy, one2, none2, eps2;
        PACKF(xx, xc.x, xc.x);
        PACKF(yy, xc.y, xc.y);
        PACKF(one2, 1.0f, 1.0f);
        PACKF(none2, -1.0f, -1.0f);
        PACKF(eps2, 1e-12f, 1e-12f);

        ull racc0, racc1;
        PACKF(racc0, 0.f, 0.f);
        PACKF(racc1, 0.f, 0.f);

        #pragma unroll 4
        for (int j = 0; j < Kc / 2; j += 2) {
            {   // pair j
                ull ox = sxn[j], oy = syn[j], oq = sqz[j];
                ull dx; ADD2(dx, xx, ox);
                ull dy; ADD2(dy, yy, oy);
                ull t0; FMA2(t0, dy, dy, eps2);
                ull d2; FMA2(d2, dx, dx, t0);
                float d2a, d2b; UNPACKF(d2a, d2b, d2);
                float ra = rsq(d2a), rb = rsq(d2b);
                ull rp; PACKF(rp, ra, rb);
                ull ds; MUL2(ds, d2, rp);
                ull tp; FMA2(tp, ds, none2, one2);
                float ta, tb; UNPACKF(ta, tb, tp);
                ta = fmaxf(ta, 0.f); tb = fmaxf(tb, 0.f);
                ull tr; PACKF(tr, ta, tb);
                FMA2(racc0, oq, tr, racc0);
            }
            {   // pair j+1
                ull ox = sxn[j + 1], oy = syn[j + 1], oq = sqz[j + 1];
                ull dx; ADD2(dx, xx, ox);
                ull dy; ADD2(dy, yy, oy);
                ull t0; FMA2(t0, dy, dy, eps2);
                ull d2; FMA2(d2, dx, dx, t0);
                float d2a, d2b; UNPACKF(d2a, d2b, d2);
                float ra = rsq(d2a), rb = rsq(d2b);
                ull rp; PACKF(rp, ra, rb);
                ull ds; MUL2(ds, d2, rp);
                ull tp; FMA2(tp, ds, none2, one2);
                float ta, tb; UNPACKF(ta, tb, tp);
                ta = fmaxf(ta, 0.f); tb = fmaxf(tb, 0.f);
                ull tr; PACKF(tr, ta, tb);
                FMA2(racc1, oq, tr, racc1);
            }
        }
        ull rsum; ADD2(rsum, racc0, racc1);
        float r0, r1; UNPACKF(r0, r1, rsum);
        float total = r0 + r1;

        int obj = t_idx[i] - 1;
        if (obj >= 0) {   // remove member term from rep; add attractive term
            float oxn = ((const float*)sxn)[obj];
            float oyn = ((const float*)syn)[obj];
            float oqz = ((const float*)sqz)[obj];
            float dx = xc.x + oxn, dy = xc.y + oyn;
            float d2 = fmaf(dx, dx, fmaf(dy, dy, 1e-12f));
            float dist = d2 * rsq(d2);
            total -= oqz * fmaxf(1.0f - dist, 0.0f);
            att = q * oqz * d2;
        }
        rep = q * total;
    }

    // block reduce att, rep
    float v0 = att, v1 = rep;
    #pragma unroll
    for (int off = 16; off > 0; off >>= 1) {
        v0 += __shfl_down_sync(0xFFFFFFFFu, v0, off);
        v1 += __shfl_down_sync(0xFFFFFFFFu, v1, off);
    }
    int wid = t >> 5, lid = t & 31;
    if (lid == 0) { sr[0][wid] = v0; sr[1][wid] = v1; }
    __syncthreads();
    if (t == 0) {
        float s0 = 0.f, s1 = 0.f;
        #pragma unroll
        for (int w = 0; w < 8; ++w) { s0 += sr[0][w]; s1 += sr[1][w]; }
        atomicAdd(&g_acc[0], (double)s0);
        atomicAdd(&g_acc[1], (double)s1);
        __threadfence();
        unsigned int done = atomicAdd(&g_done, 1u);
        s_last = (done == (unsigned int)(TOTAL_BLOCKS - 1));
    }
    __syncthreads();
    if (!s_last) return;

    // ------------- last block: finalize + reset scratch -------------
    __threadfence();
    float exs = 0.f, bos = 0.f;
    for (int e = t; e < Bc * Kc; e += 256) {
        ull key = g_cand[e];
        if (key != 0ULL) {
            int bb = e / Kc;
            unsigned int nn = 0xFFFFFFFFu - (unsigned int)key;
            int ii = bb * Nc + (int)nn;
            exs += 1.0f;
            bos += 1.0f - clipb(beta[ii]);
        }
    }
    #pragma unroll
    for (int off = 16; off > 0; off >>= 1) {
        exs += __shfl_down_sync(0xFFFFFFFFu, exs, off);
        bos += __shfl_down_sync(0xFFFFFFFFu, bos, off);
    }
    __syncthreads();   // sr reuse
    if (lid == 0) { sr[0][wid] = exs; sr[1][wid] = bos; }
    __syncthreads();
    if (t == 0) {
        float e0 = 0.f, b0 = 0.f;
        #pragma unroll
        for (int w = 0; w < 8; ++w) { e0 += sr[0][w]; b0 += sr[1][w]; }
        volatile double* va = g_acc;
        double ntot   = (double)(Bc * Nc);
        double L_att  = va[0] / ntot;
        double L_rep  = va[1] / ntot;
        double n_obj  = fmax((double)e0, 1.0);
        double L_bobj = (double)b0 / n_obj;
        double n_noi  = fmax(va[3], 1.0);
        double L_noi  = va[2] / n_noi;
        double psum   = fmax(va[4], 1e-6);
        double L_e    = va[5] / psum;
        double L_p    = va[6] / psum;
        double L_t    = va[7] / psum;
        out[0] = (float)(L_att + L_rep + (L_bobj + L_noi) + L_e + L_p + L_t);
    }
    __syncthreads();
    // reset for next graph replay (globals are zero at load, so call 1 is clean too)
    for (int e = t; e < Bc * Kc; e += 256) g_cand[e] = 0ULL;
    if (t < 8) g_acc[t] = 0.0;
    if (t == 0) g_done = 0u;
}

// ---------------- launch ------------------------------------------------------
extern "C" void kernel_launch(void* const* d_in, const int* in_sizes, int n_in,
                              void* d_out, int out_size) {
    const float* beta        = (const float*)d_in[0];
    const float* ccoords     = (const float*)d_in[1];
    const float* pred_energy = (const float*)d_in[2];
    const float* pred_pos    = (const float*)d_in[3];
    const float* pred_time   = (const float*)d_in[4];
    const float* t_energy    = (const float*)d_in[5];
    const float* t_pos       = (const float*)d_in[6];
    const float* t_time      = (const float*)d_in[7];
    const int*   t_idx       = (const int*)d_in[8];
    float* out = (float*)d_out;

    dim3 grid(GRID_N, Bc);
    k_pass1<<<grid, 256>>>(beta, t_idx, pred_energy, pred_pos, pred_time,
                           t_energy, t_pos, t_time);
    k_pair<<<grid, 256>>>(beta, ccoords, t_idx, out);
}

// round 11
// speedup vs baseline: 1.9358x; 1.8318x over previous
#include <cuda_runtime.h>
#include <math.h>

#define Bc 4
#define Nc 100000
#define Kc 128
#define Q_MIN 0.5f
#define HUBER_D 2.0f
#define EPS_CLIP 1e-4f

#define P1_BLOCKS 37                         // pass1: grid (37, 4) = 148 blocks
#define GRID_N ((Nc + 255) / 256)            // 391
#define TOTAL_BLOCKS (GRID_N * Bc)           // 1564 (k_pair)

typedef unsigned long long ull;

// ---------------- device scratch (zero at load; finalizer re-zeros) ----------
__device__ ull          g_cand[Bc * Kc];     // packed (beta_bits<<32)|(~n)
__device__ double       g_acc[8];            // 0=att 1=rep 2=nb 3=nc 4=ps 5=pE 6=pPos 7=pT
__device__ unsigned int g_done;

__device__ __forceinline__ float sqa(float x) {            // MUFU.SQRT, 1 op
    float r; asm("sqrt.approx.f32 %0, %1;" : "=f"(r) : "f"(x)); return r;
}
__device__ __forceinline__ float clipb(float b) {
    return fminf(fmaxf(b, EPS_CLIP), 1.0f - EPS_CLIP);
}

// ---------------- kernel 1: block-local argmax + payload losses --------------
__global__ void __launch_bounds__(256)
k_pass1(const float* __restrict__ beta,
        const int*   __restrict__ t_idx,
        const float* __restrict__ pred_energy,
        const float* __restrict__ pred_pos,
        const float* __restrict__ pred_time,
        const float* __restrict__ t_energy,
        const float* __restrict__ t_pos,
        const float* __restrict__ t_time) {
    __shared__ ull   sc[Kc];
    __shared__ float sred[6][8];
    const int b = blockIdx.y;
    const int t = threadIdx.x;
    if (t < Kc) sc[t] = 0ULL;
    __syncthreads();

    float nb = 0.f, nc = 0.f, ps = 0.f, pes = 0.f, pps = 0.f, pts = 0.f;
    for (int n = blockIdx.x * 256 + t; n < Nc; n += P1_BLOCKS * 256) {
        int i  = b * Nc + n;
        int ti = t_idx[i];
        float bc = clipb(beta[i]);
        if (ti > 0) {   // member hit: feed block-local segment argmax (smem atomics)
            ull key = ((ull)__float_as_uint(bc) << 32)
                    | (ull)(0xFFFFFFFFu - (unsigned int)n);
            atomicMax(&sc[ti - 1], key);
        }
        float a = atanhf(bc);
        float noise = (ti == 0) ? 1.0f : 0.0f;
        float p = a * a * (1.0f - noise);
        nc += noise;
        nb += bc * noise;
        float de  = pred_energy[i] - t_energy[i];
        float ade = fabsf(de);
        float hub = (ade <= HUBER_D) ? 0.5f * de * de
                                     : HUBER_D * (ade - 0.5f * HUBER_D);
        float2 pp2 = ((const float2*)pred_pos)[i];
        float2 tp2 = ((const float2*)t_pos)[i];
        float d0 = pp2.x - tp2.x, d1 = pp2.y - tp2.y;
        float dtm = pred_time[i] - t_time[i];
        ps  += p;
        pes += p * hub;
        pps += p * (d0 * d0 + d1 * d1);
        pts += p * dtm * dtm;
    }
    __syncthreads();
    if (t < Kc) {  // flush: 148 blocks * <=128 entries = ~19k global atomics
        ull k = sc[t];
        if (k != 0ULL) atomicMax(&g_cand[b * Kc + t], k);
    }

    float v[6] = {nb, nc, ps, pes, pps, pts};
    #pragma unroll
    for (int off = 16; off > 0; off >>= 1)
        #pragma unroll
        for (int j = 0; j < 6; ++j)
            v[j] += __shfl_down_sync(0xFFFFFFFFu, v[j], off);
    int wid = t >> 5, lid = t & 31;
    if (lid == 0)
        #pragma unroll
        for (int j = 0; j < 6; ++j) sred[j][wid] = v[j];
    __syncthreads();
    if (t < 6) {
        float s = 0.f;
        #pragma unroll
        for (int w = 0; w < 8; ++w) s += sred[t][w];
        atomicAdd(&g_acc[2 + t], (double)s);
    }
}

// ---------------- kernel 2: pair loop + fused finalize ------------------------
__global__ void __launch_bounds__(256)
k_pair(const float* __restrict__ beta,
       const float* __restrict__ ccoords,
       const int*   __restrict__ t_idx,
       float*       __restrict__ out) {
    __shared__ float4 so[Kc];          // x, y, q_alpha*exists, pad
    __shared__ float  s_sumq;
    __shared__ float  sr[2][8];
    __shared__ bool   s_last;

    const int b = blockIdx.y;
    const int t = threadIdx.x;

    // gather condensation points (L2-cached after first block)
    if (t < Kc) {
        ull key = g_cand[b * Kc + t];
        float4 o = make_float4(0.f, 0.f, 0.f, 0.f);
        if (key != 0ULL) {
            unsigned int nn = 0xFFFFFFFFu - (unsigned int)key;
            int ii = b * Nc + (int)nn;
            float bcp = clipb(beta[ii]);
            float a   = atanhf(bcp);
            float2 c  = ((const float2*)ccoords)[ii];
            o = make_float4(c.x, c.y, fmaf(a, a, Q_MIN), 0.f);
        }
        so[t] = o;
    }
    __syncthreads();
    if (t < 32) {   // sum of q_alpha over all objects (missing objects have z=0)
        float s = so[t].z + so[t + 32].z + so[t + 64].z + so[t + 96].z;
        #pragma unroll
        for (int off = 16; off > 0; off >>= 1)
            s += __shfl_down_sync(0xFFFFFFFFu, s, off);
        if (t == 0) s_sumq = s;
    }
    __syncthreads();

    float att = 0.f, rep = 0.f;
    const int n = blockIdx.x * 256 + t;
    if (n < Nc) {
        int i = b * Nc + n;
        float bc = clipb(beta[i]);
        float a  = atanhf(bc);
        float q  = fmaf(a, a, Q_MIN);
        float2 xc = ((const float2*)ccoords)[i];

        // racc = sum_k q_k * sqrt(min(d2_k, 1));  rep_k = q_k - that term
        float r0 = 0.f, r1 = 0.f, r2 = 0.f, r3 = 0.f;
        #pragma unroll 4
        for (int k = 0; k < Kc; k += 4) {
            {
                float4 o = so[k];
                float dx = xc.x - o.x, dy = xc.y - o.y;
                float d2 = fmaf(dx, dx, fmaf(dy, dy, 1e-12f));
                r0 = fmaf(o.z, sqa(fminf(d2, 1.0f)), r0);
            }
            {
                float4 o = so[k + 1];
                float dx = xc.x - o.x, dy = xc.y - o.y;
                float d2 = fmaf(dx, dx, fmaf(dy, dy, 1e-12f));
                r1 = fmaf(o.z, sqa(fminf(d2, 1.0f)), r1);
            }
            {
                float4 o = so[k + 2];
                float dx = xc.x - o.x, dy = xc.y - o.y;
                float d2 = fmaf(dx, dx, fmaf(dy, dy, 1e-12f));
                r2 = fmaf(o.z, sqa(fminf(d2, 1.0f)), r2);
            }
            {
                float4 o = so[k + 3];
                float dx = xc.x - o.x, dy = xc.y - o.y;
                float d2 = fmaf(dx, dx, fmaf(dy, dy, 1e-12f));
                r3 = fmaf(o.z, sqa(fminf(d2, 1.0f)), r3);
            }
        }
        float total = s_sumq - ((r0 + r1) + (r2 + r3));

        int obj = t_idx[i] - 1;
        if (obj >= 0) {   // remove member term from rep; add attractive term
            float4 o = so[obj];
            float dx = xc.x - o.x, dy = xc.y - o.y;
            float d2 = fmaf(dx, dx, fmaf(dy, dy, 1e-12f));
            total -= o.z * (1.0f - sqa(fminf(d2, 1.0f)));
            att = q * o.z * d2;
        }
        rep = q * total;
    }

    // block reduce att, rep
    float v0 = att, v1 = rep;
    #pragma unroll
    for (int off = 16; off > 0; off >>= 1) {
        v0 += __shfl_down_sync(0xFFFFFFFFu, v0, off);
        v1 += __shfl_down_sync(0xFFFFFFFFu, v1, off);
    }
    int wid = t >> 5, lid = t & 31;
    if (lid == 0) { sr[0][wid] = v0; sr[1][wid] = v1; }
    __syncthreads();
    if (t == 0) {
        float s0 = 0.f, s1 = 0.f;
        #pragma unroll
        for (int w = 0; w < 8; ++w) { s0 += sr[0][w]; s1 += sr[1][w]; }
        atomicAdd(&g_acc[0], (double)s0);
        atomicAdd(&g_acc[1], (double)s1);
        __threadfence();
        unsigned int done = atomicAdd(&g_done, 1u);
        s_last = (done == (unsigned int)(TOTAL_BLOCKS - 1));
    }
    __syncthreads();
    if (!s_last) return;

    // ------------- last block: finalize + reset scratch -------------
    __threadfence();
    float exs = 0.f, bos = 0.f;
    for (int e = t; e < Bc * Kc; e += 256) {
        ull key = g_cand[e];
        if (key != 0ULL) {
            int bb = e / Kc;
            unsigned int nn = 0xFFFFFFFFu - (unsigned int)key;
            int ii = bb * Nc + (int)nn;
            exs += 1.0f;
            bos += 1.0f - clipb(beta[ii]);
        }
    }
    #pragma unroll
    for (int off = 16; off > 0; off >>= 1) {
        exs += __shfl_down_sync(0xFFFFFFFFu, exs, off);
        bos += __shfl_down_sync(0xFFFFFFFFu, bos, off);
    }
    __syncthreads();   // sr reuse
    if (lid == 0) { sr[0][wid] = exs; sr[1][wid] = bos; }
    __syncthreads();
    if (t == 0) {
        float e0 = 0.f, b0 = 0.f;
        #pragma unroll
        for (int w = 0; w < 8; ++w) { e0 += sr[0][w]; b0 += sr[1][w]; }
        volatile double* va = g_acc;
        double ntot   = (double)(Bc * Nc);
        double L_att  = va[0] / ntot;
        double L_rep  = va[1] / ntot;
        double n_obj  = fmax((double)e0, 1.0);
        double L_bobj = (double)b0 / n_obj;
        double n_noi  = fmax(va[3], 1.0);
        double L_noi  = va[2] / n_noi;
        double psum   = fmax(va[4], 1e-6);
        double L_e    = va[5] / psum;
        double L_p    = va[6] / psum;
        double L_t    = va[7] / psum;
        out[0] = (float)(L_att + L_rep + (L_bobj + L_noi) + L_e + L_p + L_t);
    }
    __syncthreads();
    // reset for next graph replay (globals zero at load, so call 1 is clean too)
    for (int e = t; e < Bc * Kc; e += 256) g_cand[e] = 0ULL;
    if (t < 8) g_acc[t] = 0.0;
    if (t == 0) g_done = 0u;
}

// ---------------- launch ------------------------------------------------------
extern "C" void kernel_launch(void* const* d_in, const int* in_sizes, int n_in,
                              void* d_out, int out_size) {
    const float* beta        = (const float*)d_in[0];
    const float* ccoords     = (const float*)d_in[1];
    const float* pred_energy = (const float*)d_in[2];
    const float* pred_pos    = (const float*)d_in[3];
    const float* pred_time   = (const float*)d_in[4];
    const float* t_energy    = (const float*)d_in[5];
    const float* t_pos       = (const float*)d_in[6];
    const float* t_time      = (const float*)d_in[7];
    const int*   t_idx       = (const int*)d_in[8];
    float* out = (float*)d_out;

    dim3 g1(P1_BLOCKS, Bc);
    k_pass1<<<g1, 256>>>(beta, t_idx, pred_energy, pred_pos, pred_time,
                         t_energy, t_pos, t_time);
    dim3 g2(GRID_N, Bc);
    k_pair<<<g2, 256>>>(beta, ccoords, t_idx, out);
}

// round 12
// speedup vs baseline: 2.0650x; 1.0667x over previous
#include <cuda_runtime.h>
#include <math.h>

#define Bc 4
#define Nc 100000
#define Kc 128
#define Q_MIN 0.5f
#define HUBER_D 2.0f
#define EPS_CLIP 1e-4f

#define P1_BLOCKS 37                         // pass1: grid (37, 4) = 148 blocks
#define GRID_N ((Nc + 255) / 256)            // 391
#define TOTAL_BLOCKS (GRID_N * Bc)           // 1564 (k_pair)

typedef unsigned long long ull;

// ---------------- device scratch (zero at load; finalizer re-zeros) ----------
__device__ ull          g_cand[Bc * Kc];     // packed (beta_bits<<32)|(~n)
__device__ float4       g_obj[Bc * Kc];      // x, y, q_alpha*exists, 0
__device__ float        g_sumq[Bc];
__device__ double       g_acc[10];           // 0=att 1=rep 2=nb 3=nc 4=ps 5=pE 6=pPos 7=pT 8=exs 9=bos
__device__ unsigned int g_done;

__device__ __forceinline__ float sqa(float x) {            // MUFU.SQRT
    float r; asm("sqrt.approx.f32 %0, %1;" : "=f"(r) : "f"(x)); return r;
}
__device__ __forceinline__ float clipb(float b) {
    return fminf(fmaxf(b, EPS_CLIP), 1.0f - EPS_CLIP);
}
// atanh(x) = 0.5*ln((1+x)/(1-x)) = 0.34657359*log2((1+x)/(1-x)); x in [1e-4, 1-1e-4]
__device__ __forceinline__ float fast_atanh(float x) {
    float r = __fdividef(1.0f + x, 1.0f - x);
    return 0.34657359f * __log2f(r);
}

// ---------------- kernel 1: block-local argmax + payload losses --------------
__global__ void __launch_bounds__(256)
k_pass1(const float* __restrict__ beta,
        const int*   __restrict__ t_idx,
        const float* __restrict__ pred_energy,
        const float* __restrict__ pred_pos,
        const float* __restrict__ pred_time,
        const float* __restrict__ t_energy,
        const float* __restrict__ t_pos,
        const float* __restrict__ t_time) {
    __shared__ ull   sc[Kc];
    __shared__ float sred[6][8];
    const int b = blockIdx.y;
    const int t = threadIdx.x;
    if (t < Kc) sc[t] = 0ULL;
    __syncthreads();

    float nb = 0.f, nc = 0.f, ps = 0.f, pes = 0.f, pps = 0.f, pts = 0.f;
    for (int n = blockIdx.x * 256 + t; n < Nc; n += P1_BLOCKS * 256) {
        int i  = b * Nc + n;
        int ti = t_idx[i];
        float bc = clipb(beta[i]);
        if (ti > 0) {   // block-local segment argmax (smem atomics, spread addr)
            ull key = ((ull)__float_as_uint(bc) << 32)
                    | (ull)(0xFFFFFFFFu - (unsigned int)n);
            atomicMax(&sc[ti - 1], key);
        }
        float a = fast_atanh(bc);
        float noise = (ti == 0) ? 1.0f : 0.0f;
        float p = a * a * (1.0f - noise);
        nc += noise;
        nb += bc * noise;
        float de  = pred_energy[i] - t_energy[i];
        float ade = fabsf(de);
        float hub = (ade <= HUBER_D) ? 0.5f * de * de
                                     : HUBER_D * (ade - 0.5f * HUBER_D);
        float2 pp2 = ((const float2*)pred_pos)[i];
        float2 tp2 = ((const float2*)t_pos)[i];
        float d0 = pp2.x - tp2.x, d1 = pp2.y - tp2.y;
        float dtm = pred_time[i] - t_time[i];
        ps  += p;
        pes += p * hub;
        pps += p * (d0 * d0 + d1 * d1);
        pts += p * dtm * dtm;
    }
    __syncthreads();
    if (t < Kc) {  // flush: 148 blocks * <=128 entries = ~19k global atomics
        ull k = sc[t];
        if (k != 0ULL) atomicMax(&g_cand[b * Kc + t], k);
    }

    float v[6] = {nb, nc, ps, pes, pps, pts};
    #pragma unroll
    for (int off = 16; off > 0; off >>= 1)
        #pragma unroll
        for (int j = 0; j < 6; ++j)
            v[j] += __shfl_down_sync(0xFFFFFFFFu, v[j], off);
    int wid = t >> 5, lid = t & 31;
    if (lid == 0)
        #pragma unroll
        for (int j = 0; j < 6; ++j) sred[j][wid] = v[j];
    __syncthreads();
    if (t < 6) {
        float s = 0.f;
        #pragma unroll
        for (int w = 0; w < 8; ++w) s += sred[t][w];
        atomicAdd(&g_acc[2 + t], (double)s);
    }
}

// ---------------- kernel 1.5: build condensation points ONCE ------------------
__global__ void __launch_bounds__(512)
k_prep(const float* __restrict__ beta,
       const float* __restrict__ ccoords) {
    __shared__ float sq[512];
    __shared__ float sred[2][16];
    const int t = threadIdx.x;          // t = b*128 + k
    const int b = t >> 7;

    ull key = g_cand[t];
    float4 o = make_float4(0.f, 0.f, 0.f, 0.f);
    float exf = 0.f, bobj = 0.f;
    if (key != 0ULL) {
        unsigned int nn = 0xFFFFFFFFu - (unsigned int)key;
        int ii = b * Nc + (int)nn;
        float bc = clipb(beta[ii]);
        float a  = fast_atanh(bc);
        float2 c = ((const float2*)ccoords)[ii];
        o = make_float4(c.x, c.y, fmaf(a, a, Q_MIN), 0.f);
        exf  = 1.f;
        bobj = 1.f - bc;
    }
    g_obj[t] = o;

    // per-batch sum of q_alpha
    sq[t] = o.z;
    __syncthreads();
    #pragma unroll
    for (int off = 64; off >= 1; off >>= 1) {
        if ((t & 127) < off) sq[t] += sq[t + off];
        __syncthreads();
    }
    if ((t & 127) == 0) g_sumq[b] = sq[t];

    // block-wide sums of exists / (1-beta_alpha)
    float e = exf, bo = bobj;
    #pragma unroll
    for (int off = 16; off > 0; off >>= 1) {
        e  += __shfl_down_sync(0xFFFFFFFFu, e, off);
        bo += __shfl_down_sync(0xFFFFFFFFu, bo, off);
    }
    int wid = t >> 5, lid = t & 31;
    if (lid == 0) { sred[0][wid] = e; sred[1][wid] = bo; }
    __syncthreads();
    if (t == 0) {
        float es = 0.f, bs = 0.f;
        #pragma unroll
        for (int w = 0; w < 16; ++w) { es += sred[0][w]; bs += sred[1][w]; }
        g_acc[8] = (double)es;
        g_acc[9] = (double)bs;
    }
}

// ---------------- kernel 2: pair loop + fused finalize ------------------------
__global__ void __launch_bounds__(256)
k_pair(const float* __restrict__ beta,
       const float* __restrict__ ccoords,
       const int*   __restrict__ t_idx,
       float*       __restrict__ out) {
    __shared__ float sx[Kc], sy[Kc], sq[Kc];
    __shared__ float sr[2][8];
    __shared__ bool  s_last;

    const int b = blockIdx.y;
    const int t = threadIdx.x;

    if (t < Kc) {   // coalesced, precomputed — no atanh, no gather chase
        float4 o = g_obj[b * Kc + t];
        sx[t] = o.x; sy[t] = o.y; sq[t] = o.z;
    }
    const float sumq = g_sumq[b];       // uniform, L1/L2-cached
    __syncthreads();

    float att = 0.f, rep = 0.f;
    const int n = blockIdx.x * 256 + t;
    if (n < Nc) {
        int i = b * Nc + n;
        float bc = clipb(beta[i]);
        float a  = fast_atanh(bc);
        float q  = fmaf(a, a, Q_MIN);
        float2 xc = ((const float2*)ccoords)[i];
        const float cx = xc.x, cy = xc.y;

        const float4* px = (const float4*)sx;
        const float4* py = (const float4*)sy;
        const float4* pq = (const float4*)sq;

        // racc = sum_k q_k * min(dist_k, 1);  rep = q * (sumq - racc) (+member fix)
        float r0 = 0.f, r1 = 0.f, r2 = 0.f, r3 = 0.f;
        #pragma unroll 8
        for (int j = 0; j < Kc / 4; ++j) {
            float4 xv = px[j], yv = py[j], qv = pq[j];
            float dx, dy, d2;
            dx = cx - xv.x; dy = cy - yv.x; d2 = fmaf(dx, dx, dy * dy);
            r0 = fmaf(qv.x, sqa(fminf(d2, 1.0f)), r0);
            dx = cx - xv.y; dy = cy - yv.y; d2 = fmaf(dx, dx, dy * dy);
            r1 = fmaf(qv.y, sqa(fminf(d2, 1.0f)), r1);
            dx = cx - xv.z; dy = cy - yv.z; d2 = fmaf(dx, dx, dy * dy);
            r2 = fmaf(qv.z, sqa(fminf(d2, 1.0f)), r2);
            dx = cx - xv.w; dy = cy - yv.w; d2 = fmaf(dx, dx, dy * dy);
            r3 = fmaf(qv.w, sqa(fminf(d2, 1.0f)), r3);
        }
        float total = sumq - ((r0 + r1) + (r2 + r3));

        int obj = t_idx[i] - 1;
        if (obj >= 0) {   // remove member term from rep; add attractive term
            float ox = sx[obj], oy = sy[obj], oq = sq[obj];
            float dx = cx - ox, dy = cy - oy;
            float d2 = fmaf(dx, dx, dy * dy);
            total -= oq * (1.0f - sqa(fminf(d2, 1.0f)));
            att = q * oq * d2;
        }
        rep = q * total;
    }

    // block reduce att, rep
    float v0 = att, v1 = rep;
    #pragma unroll
    for (int off = 16; off > 0; off >>= 1) {
        v0 += __shfl_down_sync(0xFFFFFFFFu, v0, off);
        v1 += __shfl_down_sync(0xFFFFFFFFu, v1, off);
    }
    int wid = t >> 5, lid = t & 31;
    if (lid == 0) { sr[0][wid] = v0; sr[1][wid] = v1; }
    __syncthreads();
    if (t == 0) {
        float s0 = 0.f, s1 = 0.f;
        #pragma unroll
        for (int w = 0; w < 8; ++w) { s0 += sr[0][w]; s1 += sr[1][w]; }
        atomicAdd(&g_acc[0], (double)s0);
        atomicAdd(&g_acc[1], (double)s1);
        __threadfence();
        unsigned int done = atomicAdd(&g_done, 1u);
        s_last = (done == (unsigned int)(TOTAL_BLOCKS - 1));
    }
    __syncthreads();
    if (!s_last) return;

    // ------------- last block: finalize + reset scratch -------------
    __threadfence();
    if (t == 0) {
        volatile double* va = g_acc;
        double ntot   = (double)(Bc * Nc);
        double L_att  = va[0] / ntot;
        double L_rep  = va[1] / ntot;
        double n_obj  = fmax(va[8], 1.0);
        double L_bobj = va[9] / n_obj;
        double n_noi  = fmax(va[3], 1.0);
        double L_noi  = va[2] / n_noi;
        double psum   = fmax(va[4], 1e-6);
        double L_e    = va[5] / psum;
        double L_p    = va[6] / psum;
        double L_t    = va[7] / psum;
        out[0] = (float)(L_att + L_rep + (L_bobj + L_noi) + L_e + L_p + L_t);
    }
    __syncthreads();
    // reset for next graph replay (globals zero at load, so call 1 is clean too)
    for (int e = t; e < Bc * Kc; e += 256) g_cand[e] = 0ULL;
    if (t < 10) g_acc[t] = 0.0;
    if (t == 0) g_done = 0u;
}

// ---------------- launch ------------------------------------------------------
extern "C" void kernel_launch(void* const* d_in, const int* in_sizes, int n_in,
                              void* d_out, int out_size) {
    const float* beta        = (const float*)d_in[0];
    const float* ccoords     = (const float*)d_in[1];
    const float* pred_energy = (const float*)d_in[2];
    const float* pred_pos    = (const float*)d_in[3];
    const float* pred_time   = (const float*)d_in[4];
    const float* t_energy    = (const float*)d_in[5];
    const float* t_pos       = (const float*)d_in[6];
    const float* t_time      = (const float*)d_in[7];
    const int*   t_idx       = (const int*)d_in[8];
    float* out = (float*)d_out;

    dim3 g1(P1_BLOCKS, Bc);
    k_pass1<<<g1, 256>>>(beta, t_idx, pred_energy, pred_pos, pred_time,
                         t_energy, t_pos, t_time);
    k_prep<<<1, 512>>>(beta, ccoords);
    dim3 g2(GRID_N, Bc);
    k_pair<<<g2, 256>>>(beta, ccoords, t_idx, out);
}

// round 13
// speedup vs baseline: 2.1449x; 1.0387x over previous
#include <cuda_runtime.h>
#include <math.h>

#define Bc 4
#define Nc 100000
#define Kc 128
#define Q_MIN 0.5f
#define HUBER_D 2.0f
#define EPS_CLIP 1e-4f

#define ARG_BLOCKS 148                       // argmax: grid (148, 4) = 592 blocks
#define GRID_N ((Nc + 255) / 256)            // 391
#define TOTAL_BLOCKS (GRID_N * Bc)           // 1564 (k_pair)

typedef unsigned long long ull;

// ---------------- device scratch (zero at load; finalizer re-zeros) ----------
__device__ ull          g_cand[Bc * Kc];     // packed (beta_bits<<32)|(~n)
__device__ float4       g_obj[Bc * Kc];      // x, y, q_alpha*exists, 0
__device__ float        g_sumq[Bc];
__device__ double       g_acc[10];           // 0=att 1=rep 2=nb 3=nc 4=ps 5=pE 6=pPos 7=pT 8=exs 9=bos
__device__ unsigned int g_done;

__device__ __forceinline__ float sqa(float x) {            // MUFU.SQRT
    float r; asm("sqrt.approx.f32 %0, %1;" : "=f"(r) : "f"(x)); return r;
}
__device__ __forceinline__ float clipb(float b) {
    return fminf(fmaxf(b, EPS_CLIP), 1.0f - EPS_CLIP);
}
// atanh(x) = 0.34657359*log2((1+x)/(1-x)); x in [1e-4, 1-1e-4]
__device__ __forceinline__ float fast_atanh(float x) {
    float r = __fdividef(1.0f + x, 1.0f - x);
    return 0.34657359f * __log2f(r);
}

// ---------------- kernel 1: segment argmax only -------------------------------
__global__ void __launch_bounds__(256)
k_argmax(const float* __restrict__ beta,
         const int*   __restrict__ t_idx) {
    __shared__ ull sc[Kc];
    const int b = blockIdx.y;
    const int t = threadIdx.x;
    if (t < Kc) sc[t] = 0ULL;
    __syncthreads();

    for (int n = blockIdx.x * 256 + t; n < Nc; n += ARG_BLOCKS * 256) {
        int i  = b * Nc + n;
        int ti = t_idx[i];
        float bc = clipb(beta[i]);
        if (ti > 0) {   // block-local smem argmax, spread addresses
            ull key = ((ull)__float_as_uint(bc) << 32)
                    | (ull)(0xFFFFFFFFu - (unsigned int)n);
            atomicMax(&sc[ti - 1], key);
        }
    }
    __syncthreads();
    if (t < Kc) {
        ull k = sc[t];
        if (k != 0ULL) atomicMax(&g_cand[b * Kc + t], k);
    }
}

// ---------------- kernel 1.5: build condensation points ONCE ------------------
__global__ void __launch_bounds__(512)
k_prep(const float* __restrict__ beta,
       const float* __restrict__ ccoords) {
    __shared__ float sq[512];
    __shared__ float sred[2][16];
    const int t = threadIdx.x;          // t = b*128 + k
    const int b = t >> 7;

    ull key = g_cand[t];
    float4 o = make_float4(0.f, 0.f, 0.f, 0.f);
    float exf = 0.f, bobj = 0.f;
    if (key != 0ULL) {
        unsigned int nn = 0xFFFFFFFFu - (unsigned int)key;
        int ii = b * Nc + (int)nn;
        float bc = clipb(beta[ii]);
        float a  = fast_atanh(bc);
        float2 c = ((const float2*)ccoords)[ii];
        o = make_float4(c.x, c.y, fmaf(a, a, Q_MIN), 0.f);
        exf  = 1.f;
        bobj = 1.f - bc;
    }
    g_obj[t] = o;

    // per-batch sum of q_alpha
    sq[t] = o.z;
    __syncthreads();
    #pragma unroll
    for (int off = 64; off >= 1; off >>= 1) {
        if ((t & 127) < off) sq[t] += sq[t + off];
        __syncthreads();
    }
    if ((t & 127) == 0) g_sumq[b] = sq[t];

    // sums of exists / (1-beta_alpha)
    float e = exf, bo = bobj;
    #pragma unroll
    for (int off = 16; off > 0; off >>= 1) {
        e  += __shfl_down_sync(0xFFFFFFFFu, e, off);
        bo += __shfl_down_sync(0xFFFFFFFFu, bo, off);
    }
    int wid = t >> 5, lid = t & 31;
    if (lid == 0) { sred[0][wid] = e; sred[1][wid] = bo; }
    __syncthreads();
    if (t == 0) {
        float es = 0.f, bs = 0.f;
        #pragma unroll
        for (int w = 0; w < 16; ++w) { es += sred[0][w]; bs += sred[1][w]; }
        g_acc[8] = (double)es;
        g_acc[9] = (double)bs;
    }
}

// ---------------- kernel 2: pair loop + payload + fused finalize --------------
__global__ void __launch_bounds__(256)
k_pair(const float* __restrict__ beta,
       const float* __restrict__ ccoords,
       const int*   __restrict__ t_idx,
       const float* __restrict__ pred_energy,
       const float* __restrict__ pred_pos,
       const float* __restrict__ pred_time,
       const float* __restrict__ t_energy,
       const float* __restrict__ t_pos,
       const float* __restrict__ t_time,
       float*       __restrict__ out) {
    __shared__ float sx[Kc], sy[Kc], sq[Kc];
    __shared__ float sr[8][8];
    __shared__ bool  s_last;

    const int b = blockIdx.y;
    const int t = threadIdx.x;

    if (t < Kc) {
        float4 o = g_obj[b * Kc + t];
        sx[t] = o.x; sy[t] = o.y; sq[t] = o.z;
    }
    const float sumq = g_sumq[b];
    __syncthreads();

    float att = 0.f, rep = 0.f, nb = 0.f, ncnt = 0.f;
    float ps = 0.f, pes = 0.f, pps = 0.f, pts = 0.f;
    const int n = blockIdx.x * 256 + t;
    if (n < Nc) {
        const int i = b * Nc + n;
        // issue all global loads up front — latencies hidden under the K loop
        const float bc0 = beta[i];
        const int   ti  = t_idx[i];
        const float2 xc = ((const float2*)ccoords)[i];
        const float pe  = pred_energy[i];
        const float te  = t_energy[i];
        const float2 pp2 = ((const float2*)pred_pos)[i];
        const float2 tp2 = ((const float2*)t_pos)[i];
        const float pt  = pred_time[i];
        const float tt  = t_time[i];

        const float bc = clipb(bc0);
        const float a  = fast_atanh(bc);
        const float q  = fmaf(a, a, Q_MIN);
        const float cx = xc.x, cy = xc.y;

        const float4* px = (const float4*)sx;
        const float4* py = (const float4*)sy;
        const float4* pq = (const float4*)sq;

        // racc = sum_k q_k * min(dist_k, 1)
        float r0 = 0.f, r1 = 0.f, r2 = 0.f, r3 = 0.f;
        #pragma unroll 8
        for (int j = 0; j < Kc / 4; ++j) {
            float4 xv = px[j], yv = py[j], qv = pq[j];
            float dx, dy, d2;
            dx = cx - xv.x; dy = cy - yv.x; d2 = fmaf(dx, dx, dy * dy);
            r0 = fmaf(qv.x, sqa(fminf(d2, 1.0f)), r0);
            dx = cx - xv.y; dy = cy - yv.y; d2 = fmaf(dx, dx, dy * dy);
            r1 = fmaf(qv.y, sqa(fminf(d2, 1.0f)), r1);
            dx = cx - xv.z; dy = cy - yv.z; d2 = fmaf(dx, dx, dy * dy);
            r2 = fmaf(qv.z, sqa(fminf(d2, 1.0f)), r2);
            dx = cx - xv.w; dy = cy - yv.w; d2 = fmaf(dx, dx, dy * dy);
            r3 = fmaf(qv.w, sqa(fminf(d2, 1.0f)), r3);
        }
        float total = sumq - ((r0 + r1) + (r2 + r3));

        const int obj = ti - 1;
        if (obj >= 0) {   // member fix + attractive term
            float ox = sx[obj], oy = sy[obj], oq = sq[obj];
            float dx = cx - ox, dy = cy - oy;
            float d2 = fmaf(dx, dx, dy * dy);
            total -= oq * (1.0f - sqa(fminf(d2, 1.0f)));
            att = q * oq * d2;
        }
        rep = q * total;

        // payload losses (memory already in regs)
        float noise = (ti == 0) ? 1.0f : 0.0f;
        float p = a * a * (1.0f - noise);
        ncnt = noise;
        nb   = bc * noise;
        float de  = pe - te;
        float ade = fabsf(de);
        float hub = (ade <= HUBER_D) ? 0.5f * de * de
                                     : HUBER_D * (ade - 0.5f * HUBER_D);
        float d0 = pp2.x - tp2.x, d1 = pp2.y - tp2.y;
        float dtm = pt - tt;
        ps  = p;
        pes = p * hub;
        pps = p * (d0 * d0 + d1 * d1);
        pts = p * dtm * dtm;
    }

    // ---- block reduce 8 scalars ----
    float v[8] = {att, rep, nb, ncnt, ps, pes, pps, pts};
    #pragma unroll
    for (int off = 16; off > 0; off >>= 1)
        #pragma unroll
        for (int j = 0; j < 8; ++j)
            v[j] += __shfl_down_sync(0xFFFFFFFFu, v[j], off);
    int wid = t >> 5, lid = t & 31;
    if (lid == 0)
        #pragma unroll
        for (int j = 0; j < 8; ++j) sr[j][wid] = v[j];
    __syncthreads();
    if (t < 8) {
        float s = 0.f;
        #pragma unroll
        for (int w = 0; w < 8; ++w) s += sr[t][w];
        atomicAdd(&g_acc[t], (double)s);
    }
    if (t == 0) {
        __threadfence();
        unsigned int done = atomicAdd(&g_done, 1u);
        s_last = (done == (unsigned int)(TOTAL_BLOCKS - 1));
    }
    __syncthreads();
    if (!s_last) return;

    // ------------- last block: finalize + reset scratch -------------
    __threadfence();
    if (t == 0) {
        volatile double* va = g_acc;
        double ntot   = (double)(Bc * Nc);
        double L_att  = va[0] / ntot;
        double L_rep  = va[1] / ntot;
        double n_obj  = fmax(va[8], 1.0);
        double L_bobj = va[9] / n_obj;
        double n_noi  = fmax(va[3], 1.0);
        double L_noi  = va[2] / n_noi;
        double psum   = fmax(va[4], 1e-6);
        double L_e    = va[5] / psum;
        double L_p    = va[6] / psum;
        double L_t    = va[7] / psum;
        out[0] = (float)(L_att + L_rep + (L_bobj + L_noi) + L_e + L_p + L_t);
    }
    __syncthreads();
    // reset for next graph replay (globals zero at load, so call 1 is clean too)
    for (int e = t; e < Bc * Kc; e += 256) g_cand[e] = 0ULL;
    if (t < 10) g_acc[t] = 0.0;
    if (t == 0) g_done = 0u;
}

// ---------------- launch ------------------------------------------------------
extern "C" void kernel_launch(void* const* d_in, const int* in_sizes, int n_in,
                              void* d_out, int out_size) {
    const float* beta        = (const float*)d_in[0];
    const float* ccoords     = (const float*)d_in[1];
    const float* pred_energy = (const float*)d_in[2];
    const float* pred_pos    = (const float*)d_in[3];
    const float* pred_time   = (const float*)d_in[4];
    const float* t_energy    = (const float*)d_in[5];
    const float* t_pos       = (const float*)d_in[6];
    const float* t_time      = (const float*)d_in[7];
    const int*   t_idx       = (const int*)d_in[8];
    float* out = (float*)d_out;

    dim3 g1(ARG_BLOCKS, Bc);
    k_argmax<<<g1, 256>>>(beta, t_idx);
    k_prep<<<1, 512>>>(beta, ccoords);
    dim3 g2(GRID_N, Bc);
    k_pair<<<g2, 256>>>(beta, ccoords, t_idx,
                        pred_energy, pred_pos, pred_time,
                        t_energy, t_pos, t_time, out);
}